// round 4
// baseline (speedup 1.0000x reference)
#include <cuda_runtime.h>
#include <math.h>

#define Bn 32
#define Cn 16
#define Hn 128
#define Wn 128
#define HW (Hn * Wn)
#define TS 64          // tile 64x64, 4 tiles per image, 128 blocks total
#define EX 66          // extended (+-1)
#define SX 68          // x tile (+-2)

// Border-ring exchange buffers (only ring px actually touched) + barrier counters.
__device__ float2 g_h[2][Bn * HW];
__device__ unsigned g_cnt[Bn];

typedef unsigned long long u64;

__device__ __forceinline__ u64 ffma2(u64 a, u64 b, u64 c) {
    u64 d;
    asm("fma.rn.f32x2 %0, %1, %2, %3;" : "=l"(d) : "l"(a), "l"(b), "l"(c));
    return d;
}
__device__ __forceinline__ u64 pack2(float v) {
    u64 r;
    asm("mov.b64 %0, {%1, %1};" : "=l"(r) : "f"(v));
    return r;
}
__device__ __forceinline__ u64 pack2f(float a, float b) {
    u64 r;
    asm("mov.b64 %0, {%1, %2};" : "=l"(r) : "f"(a), "f"(b));
    return r;
}
__device__ __forceinline__ void unpack2(u64 v, float& lo, float& hi) {
    asm("mov.b64 {%0, %1}, %2;" : "=f"(lo), "=f"(hi) : "l"(v));
}
__device__ __forceinline__ float tanh_fast(float x) {
    float y;
    asm("tanh.approx.f32 %0, %1;" : "=f"(y) : "f"(x));
    return y;
}
__device__ __forceinline__ float sigm(float v) {
    return fmaf(tanh_fast(0.5f * v), 0.5f, 0.5f);
}
__device__ __forceinline__ unsigned ld_acq(const unsigned* p) {
    unsigned v;
    asm volatile("ld.acquire.gpu.global.u32 %0, [%1];" : "=r"(v) : "l"(p));
    return v;
}

__device__ __forceinline__ float block_sum512(float v, float* sred) {
    #pragma unroll
    for (int o = 16; o > 0; o >>= 1) v += __shfl_down_sync(0xffffffffu, v, o);
    int lane = threadIdx.x & 31, wid = threadIdx.x >> 5;
    if (lane == 0) sred[wid] = v;
    __syncthreads();
    if (wid == 0) {
        v = (lane < 16) ? sred[lane] : 0.0f;
        #pragma unroll
        for (int o = 8; o > 0; o >>= 1) v += __shfl_down_sync(0xffffffffu, v, o);
    }
    return v;  // valid in thread 0
}

__global__ void zero_out_kernel(float* out) {
    if (threadIdx.x < Bn) { out[threadIdx.x] = 0.0f; g_cnt[threadIdx.x] = 0u; }
}

// Persistent fused ConvLSTM. Block = one 64x64 tile of one image; 4 blocks per
// image sync via a tiny per-image barrier. h state lives in smem (double
// buffered); only the 1px border ring is exchanged through global memory.
__global__ __launch_bounds__(512, 1) void lstm_kernel(
    const float* __restrict__ x,
    const float* __restrict__ Win,  const float* __restrict__ b_in,
    const float* __restrict__ Wih,  const float* __restrict__ b_ih,
    const float* __restrict__ Whh,  const float* __restrict__ b_hh,
    const float* __restrict__ Wout, const float* __restrict__ b_out,
    float* __restrict__ out)
{
    extern __shared__ float smem[];
    float* sWih  = smem;            // [72]
    float* sWhh  = smem + 72;       // [144]
    float* sWoutY= smem + 216;      // [36]
    float* sbias = smem + 252;      // [8]
    float* sWin  = smem + 260;      // [9]
    float* sbin  = smem + 269;      // [1]
    float* sbout = smem + 270;      // [2]
    float* sred  = smem + 272;      // [16]
    float* sx    = smem + 288;      // [68*68]  x tile, offset (-2,-2)
    float* szi   = smem + 4912;     // [66*66]  zi, offset (-1,-1)
    float* shp   = smem + 9268;     // [2][2][66*66] h planes: [buf][ch]

    const int tid = threadIdx.x;
    const int b = blockIdx.z;
    const int gx0 = blockIdx.x * TS, gy0 = blockIdx.y * TS;
    const int ix = tid & 63;                 // column within tile
    const int yg = (tid >> 6) << 3;          // first of 8 rows handled

    // ---- weights -> smem (once) ----
    if (tid < 144) sWhh[tid] = Whh[tid];
    if (tid < 72)  sWih[tid] = Wih[tid];
    if (tid < 36) {  // Wout_y = Wout[:,:,:2,:], src flat (k*4+ci)*2+co
        int k = tid >> 2, ci = (tid >> 1) & 1, co = tid & 1;
        sWoutY[tid] = Wout[(k * 4 + ci) * 2 + co];
    }
    if (tid < 9) sWin[tid] = Win[tid];
    if (tid < 8) sbias[tid] = b_ih[tid] + b_hh[tid];
    if (tid < 2) sbout[tid] = b_out[tid];
    if (tid == 0) sbin[0] = b_in[0];
    // h_0 = 0 (both buffers fully zeroed once; ring stays 0 at image edges)
    for (int i = tid; i < 4 * EX * EX; i += 512) shp[i] = 0.0f;

    float c0[8], c1[8];
    #pragma unroll
    for (int k = 0; k < 8; k++) { c0[k] = 0.0f; c1[k] = 0.0f; }

    // ---- prologue: load x(0), zi(0), channel-0 log-prob ----
    {
        const float* xin = x + (size_t)(b * Cn) * HW;
        for (int i = tid; i < SX * SX; i += 512) {
            int r = i / SX, c = i - r * SX;
            int gy = gy0 - 2 + r, gx = gx0 - 2 + c;
            float v = 0.0f;
            if ((unsigned)gy < Hn && (unsigned)gx < Wn) v = xin[gy * Wn + gx];
            sx[i] = v;
        }
    }
    __syncthreads();

    const u64* w1p = (const u64*)sWih;
    const u64* w2p = (const u64*)sWhh;
    const u64* wop = (const u64*)sWoutY;
    const u64* sbp = (const u64*)sbias;
    const u64 pbias = pack2f(sbout[0], sbout[1]);

    float lpacc = 0.0f;
    {
        float mu = sbout[0], ls = sbout[1];
        float e = __expf(-ls);
        #pragma unroll
        for (int k = 0; k < 8; k++) {
            float xv = sx[(yg + k + 2) * SX + ix + 2];
            float z = (xv - mu) * e;
            lpacc += -0.5f * z * z - ls - 0.9189385332046727f;
        }
    }
    // zi(0)
    {
        float bin = sbin[0];
        for (int i = tid; i < EX * EX; i += 512) {
            int r = i / EX, c = i - r * EX;
            int gy = gy0 - 1 + r, gx = gx0 - 1 + c;
            float v = 0.0f;
            if ((unsigned)gy < Hn && (unsigned)gx < Wn) {
                v = bin;
                #pragma unroll
                for (int dy = 0; dy < 3; dy++)
                    #pragma unroll
                    for (int dx = 0; dx < 3; dx++)
                        v += sx[(r + dy) * SX + (c + dx)] * sWin[dy * 3 + dx];
            }
            szi[i] = v;
        }
    }
    __syncthreads();

    for (int t = 0; t < 15; t++) {
        const int cur = t & 1, nxt = cur ^ 1;
        float* sh0  = shp + (size_t)cur * 2 * EX * EX;
        float* sh1  = sh0 + EX * EX;
        float* shn0 = shp + (size_t)nxt * 2 * EX * EX;
        float* shn1 = shn0 + EX * EX;
        float2* ghp = g_h[nxt] + (size_t)b * HW;

        // (1) gates + LSTM, interior 64x64; write h into shb[nxt] interior,
        //     border px also STG'd to global for neighbors.
        #pragma unroll
        for (int k = 0; k < 8; k++) {
            int r = yg + k;
            u64 a0 = sbp[0], a1 = sbp[1], a2 = sbp[2], a3 = sbp[3];
            #pragma unroll
            for (int dy = 0; dy < 3; dy++) {
                #pragma unroll
                for (int dx = 0; dx < 3; dx++) {
                    int si = (r + dy) * EX + ix + dx;
                    int tap = dy * 3 + dx;
                    u64 zp  = pack2(szi[si]);
                    u64 h0p = pack2(sh0[si]);
                    u64 h1p = pack2(sh1[si]);
                    a0 = ffma2(zp,  w1p[tap * 4 + 0], a0);
                    a1 = ffma2(zp,  w1p[tap * 4 + 1], a1);
                    a2 = ffma2(zp,  w1p[tap * 4 + 2], a2);
                    a3 = ffma2(zp,  w1p[tap * 4 + 3], a3);
                    a0 = ffma2(h0p, w2p[tap * 8 + 0], a0);
                    a1 = ffma2(h0p, w2p[tap * 8 + 1], a1);
                    a2 = ffma2(h0p, w2p[tap * 8 + 2], a2);
                    a3 = ffma2(h0p, w2p[tap * 8 + 3], a3);
                    a0 = ffma2(h1p, w2p[tap * 8 + 4], a0);
                    a1 = ffma2(h1p, w2p[tap * 8 + 5], a1);
                    a2 = ffma2(h1p, w2p[tap * 8 + 6], a2);
                    a3 = ffma2(h1p, w2p[tap * 8 + 7], a3);
                }
            }
            float i0, i1, g0, g1, f0, f1, o0, o1;
            unpack2(a0, i0, i1); unpack2(a1, g0, g1);
            unpack2(a2, f0, f1); unpack2(a3, o0, o1);
            float cn0 = sigm(f0 + 1.0f) * c0[k] + sigm(i0) * tanh_fast(g0);
            float cn1 = sigm(f1 + 1.0f) * c1[k] + sigm(i1) * tanh_fast(g1);
            c0[k] = cn0; c1[k] = cn1;
            float hn0 = sigm(o0) * tanh_fast(cn0);
            float hn1 = sigm(o1) * tanh_fast(cn1);
            int ei = (r + 1) * EX + ix + 1;
            shn0[ei] = hn0; shn1[ei] = hn1;
            if (r == 0 || r == 63 || ix == 0 || ix == 63)
                ghp[(gy0 + r) * Wn + gx0 + ix] = make_float2(hn0, hn1);
        }
        __syncthreads();
        // (2) arrive on per-image barrier
        if (tid == 0) { __threadfence(); atomicAdd(&g_cnt[b], 1u); }

        // (3) load x(t+1) tile (hides barrier latency)
        {
            const float* xin = x + (size_t)(b * Cn + t + 1) * HW;
            for (int i = tid; i < SX * SX; i += 512) {
                int r = i / SX, c = i - r * SX;
                int gy = gy0 - 2 + r, gx = gx0 - 2 + c;
                float v = 0.0f;
                if ((unsigned)gy < Hn && (unsigned)gx < Wn) v = xin[gy * Wn + gx];
                sx[i] = v;
            }
        }
        __syncthreads();
        // (4) zi(t+1) (also hides barrier latency)
        if (t < 14) {
            float bin = sbin[0];
            for (int i = tid; i < EX * EX; i += 512) {
                int r = i / EX, c = i - r * EX;
                int gy = gy0 - 1 + r, gx = gx0 - 1 + c;
                float v = 0.0f;
                if ((unsigned)gy < Hn && (unsigned)gx < Wn) {
                    v = bin;
                    #pragma unroll
                    for (int dy = 0; dy < 3; dy++)
                        #pragma unroll
                        for (int dx = 0; dx < 3; dx++)
                            v += sx[(r + dy) * SX + (c + dx)] * sWin[dy * 3 + dx];
                }
                szi[i] = v;
            }
        }
        // (5) wait for the other 3 blocks of this image
        if (tid == 0) {
            unsigned target = 4u * (unsigned)(t + 1);
            while (ld_acq(&g_cnt[b]) < target) { __nanosleep(64); }
        }
        __syncthreads();
        // (6) pull the halo ring of h(t+1) from neighbors (L2, bypass L1)
        if (tid < 260) {
            int rr, cc;
            if (tid < 66)       { rr = 0;              cc = tid; }
            else if (tid < 132) { rr = 65;             cc = tid - 66; }
            else if (tid < 196) { rr = 1 + (tid - 132); cc = 0; }
            else                { rr = 1 + (tid - 196); cc = 65; }
            int gy = gy0 - 1 + rr, gx = gx0 - 1 + cc;
            float2 hv = make_float2(0.0f, 0.0f);
            if ((unsigned)gy < Hn && (unsigned)gx < Wn)
                hv = __ldcg(&ghp[gy * Wn + gx]);
            shn0[rr * EX + cc] = hv.x;
            shn1[rr * EX + cc] = hv.y;
        }
        __syncthreads();
        // (7) out conv over h(t+1); log-prob vs x(t+1) (already in sx)
        #pragma unroll
        for (int k = 0; k < 8; k++) {
            int r = yg + k;
            u64 pp = pbias;
            #pragma unroll
            for (int dy = 0; dy < 3; dy++) {
                #pragma unroll
                for (int dx = 0; dx < 3; dx++) {
                    int si = (r + dy) * EX + ix + dx;
                    int tap = dy * 3 + dx;
                    pp = ffma2(pack2(shn0[si]), wop[tap * 2 + 0], pp);
                    pp = ffma2(pack2(shn1[si]), wop[tap * 2 + 1], pp);
                }
            }
            float p0, p1;
            unpack2(pp, p0, p1);
            float xv = sx[(r + 2) * SX + ix + 2];
            float e = __expf(-p1);
            float z = (xv - p0) * e;
            lpacc += -0.5f * z * z - p1 - 0.9189385332046727f;
        }
        // no sync needed: next iter writes only the other h buffer; szi/sx
        // reuse is fenced by the syncs inside the next iteration.
    }

    float tot = block_sum512(lpacc, sred);
    if (tid == 0) atomicAdd(&out[b], tot);
}

extern "C" void kernel_launch(void* const* d_in, const int* in_sizes, int n_in,
                              void* d_out, int out_size) {
    const float* x     = (const float*)d_in[0];
    const float* Win   = (const float*)d_in[1];
    const float* b_in  = (const float*)d_in[2];
    const float* Wih   = (const float*)d_in[3];
    const float* b_ih  = (const float*)d_in[4];
    const float* Whh   = (const float*)d_in[5];
    const float* b_hh  = (const float*)d_in[6];
    const float* Wout  = (const float*)d_in[7];
    const float* b_out = (const float*)d_in[8];
    float* out = (float*)d_out;

    static int smem_set = 0;
    const int smem_bytes = (9268 + 4 * EX * EX) * 4;
    if (!smem_set) {
        cudaFuncSetAttribute(lstm_kernel,
                             cudaFuncAttributeMaxDynamicSharedMemorySize,
                             smem_bytes);
        smem_set = 1;
    }

    zero_out_kernel<<<1, 32>>>(out);

    dim3 grid(Hn / TS, Wn / TS, Bn);   // 2 x 2 x 32 = 128 blocks, 1 per SM
    lstm_kernel<<<grid, 512, smem_bytes>>>(x, Win, b_in, Wih, b_ih, Whh, b_hh,
                                           Wout, b_out, out);
}

// round 5
// speedup vs baseline: 1.5530x; 1.5530x over previous
#include <cuda_runtime.h>
#include <math.h>

#define Bn 32
#define Cn 16
#define Hn 128
#define Wn 128
#define HW (Hn * Wn)
#define TW 64          // tile width
#define TH 32          // tile height; 2x4 = 8 tiles per image, 256 blocks
#define EXW 66         // extended (+-1)
#define EXH 34
#define SXW 68         // x tile (+-2)
#define SXH 36

// Border-ring exchange + per-image barrier counters.
__device__ float2 g_h[2][Bn * HW];
__device__ unsigned g_cnt[Bn];

typedef unsigned long long u64;

__device__ __forceinline__ u64 ffma2(u64 a, u64 b, u64 c) {
    u64 d;
    asm("fma.rn.f32x2 %0, %1, %2, %3;" : "=l"(d) : "l"(a), "l"(b), "l"(c));
    return d;
}
__device__ __forceinline__ u64 pack2(float v) {
    u64 r;
    asm("mov.b64 %0, {%1, %1};" : "=l"(r) : "f"(v));
    return r;
}
__device__ __forceinline__ u64 pack2f(float a, float b) {
    u64 r;
    asm("mov.b64 %0, {%1, %2};" : "=l"(r) : "f"(a), "f"(b));
    return r;
}
__device__ __forceinline__ void unpack2(u64 v, float& lo, float& hi) {
    asm("mov.b64 {%0, %1}, %2;" : "=f"(lo), "=f"(hi) : "l"(v));
}
__device__ __forceinline__ float tanh_fast(float x) {
    float y;
    asm("tanh.approx.f32 %0, %1;" : "=f"(y) : "f"(x));
    return y;
}
__device__ __forceinline__ float sigm(float v) {
    return fmaf(tanh_fast(0.5f * v), 0.5f, 0.5f);
}
__device__ __forceinline__ unsigned ld_acq(const unsigned* p) {
    unsigned v;
    asm volatile("ld.acquire.gpu.global.u32 %0, [%1];" : "=r"(v) : "l"(p));
    return v;
}

__device__ __forceinline__ float block_sum256(float v, float* sred) {
    #pragma unroll
    for (int o = 16; o > 0; o >>= 1) v += __shfl_down_sync(0xffffffffu, v, o);
    int lane = threadIdx.x & 31, wid = threadIdx.x >> 5;
    if (lane == 0) sred[wid] = v;
    __syncthreads();
    if (wid == 0) {
        v = (lane < 8) ? sred[lane] : 0.0f;
        #pragma unroll
        for (int o = 4; o > 0; o >>= 1) v += __shfl_down_sync(0xffffffffu, v, o);
    }
    return v;  // valid in thread 0
}

__global__ void zero_out_kernel(float* out) {
    if (threadIdx.x < Bn) { out[threadIdx.x] = 0.0f; g_cnt[threadIdx.x] = 0u; }
}

// Persistent fused ConvLSTM. Block = one 64x32 tile; 8 blocks per image sync
// via a per-image monotonic barrier. h state lives in smem (double-buffered);
// only the 1px border ring goes through global. 2 CTAs/SM for latency hiding.
__global__ __launch_bounds__(256, 2) void lstm_kernel(
    const float* __restrict__ x,
    const float* __restrict__ Win,  const float* __restrict__ b_in,
    const float* __restrict__ Wih,  const float* __restrict__ b_ih,
    const float* __restrict__ Whh,  const float* __restrict__ b_hh,
    const float* __restrict__ Wout, const float* __restrict__ b_out,
    float* __restrict__ out)
{
    extern __shared__ float smem[];
    float* sWih  = smem;            // [72]
    float* sWhh  = smem + 72;       // [144]
    float* sWoutY= smem + 216;      // [36]
    float* sbias = smem + 252;      // [8]
    float* sWin  = smem + 260;      // [9]
    float* sbin  = smem + 269;
    float* sbout = smem + 270;      // [2]
    float* sred  = smem + 272;      // [16]
    float* sx    = smem + 288;      // [36*68]  x, offset (-2,-2)
    float* szi   = smem + 2736;     // [34*66]  zi, offset (-1,-1)
    float* shp   = smem + 4980;     // [2][2][34*66] h: [buf][ch]

    const int tid = threadIdx.x;
    const int b = blockIdx.z;
    const int gx0 = blockIdx.x * TW, gy0 = blockIdx.y * TH;
    const int ix = tid & 63;                 // column within tile
    const int yg = (tid >> 6) << 3;          // first of 8 rows handled

    // ---- weights -> smem (once) ----
    if (tid < 144) sWhh[tid] = Whh[tid];
    if (tid < 72)  sWih[tid] = Wih[tid];
    if (tid < 36) {  // Wout_y = Wout[:,:,:2,:], src flat (k*4+ci)*2+co
        int k = tid >> 2, ci = (tid >> 1) & 1, co = tid & 1;
        sWoutY[tid] = Wout[(k * 4 + ci) * 2 + co];
    }
    if (tid < 9) sWin[tid] = Win[tid];
    if (tid < 8) sbias[tid] = b_ih[tid] + b_hh[tid];
    if (tid < 2) sbout[tid] = b_out[tid];
    if (tid == 0) sbin[0] = b_in[0];
    for (int i = tid; i < 4 * EXH * EXW; i += 256) shp[i] = 0.0f;  // h_0 = 0

    float c0[8], c1[8];
    #pragma unroll
    for (int k = 0; k < 8; k++) { c0[k] = 0.0f; c1[k] = 0.0f; }

    // ---- prologue: x(0), zi(0), channel-0 log-prob ----
    {
        const float* xin = x + (size_t)(b * Cn) * HW;
        for (int i = tid; i < SXH * SXW; i += 256) {
            int r = i / SXW, c = i - r * SXW;
            int gy = gy0 - 2 + r, gx = gx0 - 2 + c;
            float v = 0.0f;
            if ((unsigned)gy < Hn && (unsigned)gx < Wn) v = xin[gy * Wn + gx];
            sx[i] = v;
        }
    }
    __syncthreads();

    const u64* w1p = (const u64*)sWih;
    const u64* w2p = (const u64*)sWhh;
    const u64* wop = (const u64*)sWoutY;
    const u64* sbp = (const u64*)sbias;
    const u64 pbias = pack2f(sbout[0], sbout[1]);

    float lpacc = 0.0f;
    {
        float mu = sbout[0], ls = sbout[1];
        float e = __expf(-ls);
        #pragma unroll
        for (int k = 0; k < 8; k++) {
            float xv = sx[(yg + k + 2) * SXW + ix + 2];
            float z = (xv - mu) * e;
            lpacc += -0.5f * z * z - ls - 0.9189385332046727f;
        }
    }
    {
        float bin = sbin[0];
        for (int i = tid; i < EXH * EXW; i += 256) {
            int r = i / EXW, c = i - r * EXW;
            int gy = gy0 - 1 + r, gx = gx0 - 1 + c;
            float v = 0.0f;
            if ((unsigned)gy < Hn && (unsigned)gx < Wn) {
                v = bin;
                #pragma unroll
                for (int dy = 0; dy < 3; dy++)
                    #pragma unroll
                    for (int dx = 0; dx < 3; dx++)
                        v += sx[(r + dy) * SXW + (c + dx)] * sWin[dy * 3 + dx];
            }
            szi[i] = v;
        }
    }
    __syncthreads();

    for (int t = 0; t < 15; t++) {
        const int cur = t & 1, nxt = cur ^ 1;
        float* sh0  = shp + cur * 2 * EXH * EXW;
        float* sh1  = sh0 + EXH * EXW;
        float* shn0 = shp + nxt * 2 * EXH * EXW;
        float* shn1 = shn0 + EXH * EXW;
        float2* ghp = g_h[nxt] + (size_t)b * HW;

        // (1) gates + LSTM, interior, tap-outer in 2 passes of 4 rows.
        //     Weights for the current tap stay in registers across the 4 rows.
        #pragma unroll
        for (int p = 0; p < 2; p++) {
            u64 acc[4][4];
            #pragma unroll
            for (int j = 0; j < 4; j++) {
                acc[j][0] = sbp[0]; acc[j][1] = sbp[1];
                acc[j][2] = sbp[2]; acc[j][3] = sbp[3];
            }
            #pragma unroll
            for (int tap = 0; tap < 9; tap++) {
                const int dy = tap / 3, dx = tap % 3;
                u64 wz0 = w1p[tap * 4 + 0], wz1 = w1p[tap * 4 + 1];
                u64 wz2 = w1p[tap * 4 + 2], wz3 = w1p[tap * 4 + 3];
                u64 wa0 = w2p[tap * 8 + 0], wa1 = w2p[tap * 8 + 1];
                u64 wa2 = w2p[tap * 8 + 2], wa3 = w2p[tap * 8 + 3];
                u64 wb0 = w2p[tap * 8 + 4], wb1 = w2p[tap * 8 + 5];
                u64 wb2 = w2p[tap * 8 + 6], wb3 = w2p[tap * 8 + 7];
                #pragma unroll
                for (int j = 0; j < 4; j++) {
                    int si = (yg + p * 4 + j + dy) * EXW + ix + dx;
                    u64 zp  = pack2(szi[si]);
                    u64 h0p = pack2(sh0[si]);
                    u64 h1p = pack2(sh1[si]);
                    acc[j][0] = ffma2(zp,  wz0, acc[j][0]);
                    acc[j][1] = ffma2(zp,  wz1, acc[j][1]);
                    acc[j][2] = ffma2(zp,  wz2, acc[j][2]);
                    acc[j][3] = ffma2(zp,  wz3, acc[j][3]);
                    acc[j][0] = ffma2(h0p, wa0, acc[j][0]);
                    acc[j][1] = ffma2(h0p, wa1, acc[j][1]);
                    acc[j][2] = ffma2(h0p, wa2, acc[j][2]);
                    acc[j][3] = ffma2(h0p, wa3, acc[j][3]);
                    acc[j][0] = ffma2(h1p, wb0, acc[j][0]);
                    acc[j][1] = ffma2(h1p, wb1, acc[j][1]);
                    acc[j][2] = ffma2(h1p, wb2, acc[j][2]);
                    acc[j][3] = ffma2(h1p, wb3, acc[j][3]);
                }
            }
            #pragma unroll
            for (int j = 0; j < 4; j++) {
                const int k = p * 4 + j;
                int R = yg + k;
                float i0, i1, g0, g1, f0, f1, o0, o1;
                unpack2(acc[j][0], i0, i1); unpack2(acc[j][1], g0, g1);
                unpack2(acc[j][2], f0, f1); unpack2(acc[j][3], o0, o1);
                float cn0 = sigm(f0 + 1.0f) * c0[k] + sigm(i0) * tanh_fast(g0);
                float cn1 = sigm(f1 + 1.0f) * c1[k] + sigm(i1) * tanh_fast(g1);
                c0[k] = cn0; c1[k] = cn1;
                float hn0 = sigm(o0) * tanh_fast(cn0);
                float hn1 = sigm(o1) * tanh_fast(cn1);
                int ei = (R + 1) * EXW + ix + 1;
                shn0[ei] = hn0; shn1[ei] = hn1;
                if (R == 0 || R == TH - 1 || ix == 0 || ix == TW - 1)
                    ghp[(gy0 + R) * Wn + gx0 + ix] = make_float2(hn0, hn1);
            }
        }
        __syncthreads();
        // (2) arrive on per-image barrier
        if (tid == 0) { __threadfence(); atomicAdd(&g_cnt[b], 1u); }

        // (3) load x(t+1) (hides barrier latency)
        {
            const float* xin = x + (size_t)(b * Cn + t + 1) * HW;
            for (int i = tid; i < SXH * SXW; i += 256) {
                int r = i / SXW, c = i - r * SXW;
                int gy = gy0 - 2 + r, gx = gx0 - 2 + c;
                float v = 0.0f;
                if ((unsigned)gy < Hn && (unsigned)gx < Wn) v = xin[gy * Wn + gx];
                sx[i] = v;
            }
        }
        __syncthreads();
        // (4) zi(t+1) (also hides barrier latency)
        if (t < 14) {
            float bin = sbin[0];
            for (int i = tid; i < EXH * EXW; i += 256) {
                int r = i / EXW, c = i - r * EXW;
                int gy = gy0 - 1 + r, gx = gx0 - 1 + c;
                float v = 0.0f;
                if ((unsigned)gy < Hn && (unsigned)gx < Wn) {
                    v = bin;
                    #pragma unroll
                    for (int dy = 0; dy < 3; dy++)
                        #pragma unroll
                        for (int dx = 0; dx < 3; dx++)
                            v += sx[(r + dy) * SXW + (c + dx)] * sWin[dy * 3 + dx];
                }
                szi[i] = v;
            }
        }
        // (5) wait for the other 7 blocks of this image
        if (tid == 0) {
            unsigned target = 8u * (unsigned)(t + 1);
            while (ld_acq(&g_cnt[b]) < target) { __nanosleep(64); }
        }
        __syncthreads();
        // (6) pull the halo ring of h(t+1) (bypass L1)
        if (tid < 196) {
            int rr, cc;
            if (tid < 66)        { rr = 0;               cc = tid; }
            else if (tid < 132)  { rr = EXH - 1;         cc = tid - 66; }
            else if (tid < 164)  { rr = 1 + (tid - 132); cc = 0; }
            else                 { rr = 1 + (tid - 164); cc = EXW - 1; }
            int gy = gy0 - 1 + rr, gx = gx0 - 1 + cc;
            float2 hv = make_float2(0.0f, 0.0f);
            if ((unsigned)gy < Hn && (unsigned)gx < Wn)
                hv = __ldcg(&ghp[gy * Wn + gx]);
            shn0[rr * EXW + cc] = hv.x;
            shn1[rr * EXW + cc] = hv.y;
        }
        __syncthreads();
        // (7) out conv over h(t+1); log-prob vs x(t+1) (in sx)
        #pragma unroll
        for (int k = 0; k < 8; k++) {
            int R = yg + k;
            u64 pp = pbias;
            #pragma unroll
            for (int tap = 0; tap < 9; tap++) {
                const int dy = tap / 3, dx = tap % 3;
                int si = (R + dy) * EXW + ix + dx;
                pp = ffma2(pack2(shn0[si]), wop[tap * 2 + 0], pp);
                pp = ffma2(pack2(shn1[si]), wop[tap * 2 + 1], pp);
            }
            float p0, p1;
            unpack2(pp, p0, p1);
            float xv = sx[(R + 2) * SXW + ix + 2];
            float e = __expf(-p1);
            float z = (xv - p0) * e;
            lpacc += -0.5f * z * z - p1 - 0.9189385332046727f;
        }
    }

    float tot = block_sum256(lpacc, sred);
    if (tid == 0) atomicAdd(&out[b], tot);
}

extern "C" void kernel_launch(void* const* d_in, const int* in_sizes, int n_in,
                              void* d_out, int out_size) {
    const float* x     = (const float*)d_in[0];
    const float* Win   = (const float*)d_in[1];
    const float* b_in  = (const float*)d_in[2];
    const float* Wih   = (const float*)d_in[3];
    const float* b_ih  = (const float*)d_in[4];
    const float* Whh   = (const float*)d_in[5];
    const float* b_hh  = (const float*)d_in[6];
    const float* Wout  = (const float*)d_in[7];
    const float* b_out = (const float*)d_in[8];
    float* out = (float*)d_out;

    static int smem_set = 0;
    const int smem_bytes = (4980 + 4 * EXH * EXW) * 4;   // 55824 B
    if (!smem_set) {
        cudaFuncSetAttribute(lstm_kernel,
                             cudaFuncAttributeMaxDynamicSharedMemorySize,
                             smem_bytes);
        smem_set = 1;
    }

    zero_out_kernel<<<1, 32>>>(out);

    dim3 grid(Wn / TW, Hn / TH, Bn);   // 2 x 4 x 32 = 256 blocks, 2 per SM
    lstm_kernel<<<grid, 256, smem_bytes>>>(x, Win, b_in, Wih, b_ih, Whh, b_hh,
                                           Wout, b_out, out);
}